// round 2
// baseline (speedup 1.0000x reference)
#include <cuda_runtime.h>

// Problem constants (match reference)
#define N_NODES  100000
#define N_EDGES  3200000
#define D_FEAT   64
// 64 floats per row = 16 float4 chunks
#define CHUNKS   16

// ---------------------------------------------------------------------------
// Zero-init the output (harness poisons d_out with 0xAA before timing).
// ---------------------------------------------------------------------------
__global__ void zero_out_kernel(float4* __restrict__ out4, int n4) {
    int i = blockIdx.x * blockDim.x + threadIdx.x;
    if (i < n4) out4[i] = make_float4(0.f, 0.f, 0.f, 0.f);
}

// ---------------------------------------------------------------------------
// COO SpMM scatter: 16 threads per edge, one float4 chunk each.
// out[row, :] += val * x[col, :]
// Uses red.global.add.v4.f32 (sm_90+) — 16B vector reduction, no return,
// 4x fewer L2 atomic ops than scalar atomicAdd.
// NOTE: edge indices are int32 (JAX x64-disabled downcasts int64 -> int32).
// ---------------------------------------------------------------------------
__global__ void spmm_scatter_kernel(const float4* __restrict__ x4,
                                    const int* __restrict__ erow,
                                    const int* __restrict__ ecol,
                                    const float* __restrict__ eval,
                                    float* __restrict__ out) {
    long long tid = (long long)blockIdx.x * blockDim.x + threadIdx.x;
    int e = (int)(tid >> 4);       // edge index
    int c = (int)(tid & 15);       // float4 chunk within the 64-wide row
    if (e >= N_EDGES) return;

    int row = erow[e];
    int col = ecol[e];
    float v = eval[e];

    float4 xv = __ldg(&x4[(long long)col * CHUNKS + c]);
    float4 g;
    g.x = xv.x * v;
    g.y = xv.y * v;
    g.z = xv.z * v;
    g.w = xv.w * v;

    float* p = out + (long long)row * D_FEAT + c * 4;
    asm volatile("red.global.add.v4.f32 [%0], {%1, %2, %3, %4};"
                 :: "l"(p), "f"(g.x), "f"(g.y), "f"(g.z), "f"(g.w)
                 : "memory");
}

extern "C" void kernel_launch(void* const* d_in, const int* in_sizes, int n_in,
                              void* d_out, int out_size) {
    // Input order (metadata): t, x, edge_row, edge_col, edge_val
    const float* x    = (const float*)d_in[1];
    const int*   erow = (const int*)d_in[2];
    const int*   ecol = (const int*)d_in[3];
    const float* ev   = (const float*)d_in[4];
    float*       out  = (float*)d_out;

    // 1) zero the output
    {
        int n4 = (N_NODES * D_FEAT) / 4;  // 1.6M float4
        int threads = 256;
        int blocks = (n4 + threads - 1) / threads;
        zero_out_kernel<<<blocks, threads>>>((float4*)out, n4);
    }

    // 2) scatter-add SpMM
    {
        long long total = (long long)N_EDGES * CHUNKS;  // 51.2M threads
        int threads = 256;
        int blocks = (int)((total + threads - 1) / threads);
        spmm_scatter_kernel<<<blocks, threads>>>((const float4*)x, erow, ecol, ev, out);
    }
}

// round 3
// speedup vs baseline: 1.1835x; 1.1835x over previous
#include <cuda_runtime.h>

#define N_NODES  100000
#define N_EDGES  3200000
#define D_FEAT   64
#define CHUNKS   16          // 64 floats = 16 float4
#define SCAN_BLK 1024
#define N_SCANB  ((N_NODES + SCAN_BLK - 1) / SCAN_BLK)   // 98

// ------------------------- device scratch (no allocs) -----------------------
__device__ int   g_counts[N_NODES];
__device__ int   g_rowptr[N_NODES + 1];
__device__ int   g_cursor[N_NODES];
__device__ int   g_blocksum[128];
__device__ int   g_blockoff[128];
__device__ uint2 g_colval[N_EDGES];     // packed (col, val_bits) per CSR slot

// ---------------------------------------------------------------------------
// 1) zero row counters
// ---------------------------------------------------------------------------
__global__ void k_zero_counts() {
    int i = blockIdx.x * blockDim.x + threadIdx.x;
    if (i < N_NODES) g_counts[i] = 0;
}

// ---------------------------------------------------------------------------
// 2) histogram of rows
// ---------------------------------------------------------------------------
__global__ void k_hist(const int* __restrict__ erow) {
    int e = blockIdx.x * blockDim.x + threadIdx.x;
    if (e < N_EDGES) atomicAdd(&g_counts[erow[e]], 1);
}

// ---------------------------------------------------------------------------
// 3a) per-block exclusive scan of counts -> partial rowptr + block totals
// ---------------------------------------------------------------------------
__global__ void k_scan1() {
    __shared__ int s[SCAN_BLK];
    int t = threadIdx.x;
    int i = blockIdx.x * SCAN_BLK + t;
    int v = (i < N_NODES) ? g_counts[i] : 0;
    s[t] = v;
    __syncthreads();
    #pragma unroll
    for (int off = 1; off < SCAN_BLK; off <<= 1) {
        int a = (t >= off) ? s[t - off] : 0;
        __syncthreads();
        s[t] += a;
        __syncthreads();
    }
    if (i < N_NODES) g_rowptr[i] = s[t] - v;       // exclusive within block
    if (t == SCAN_BLK - 1) g_blocksum[blockIdx.x] = s[t];
}

// ---------------------------------------------------------------------------
// 3b) scan the 98 block totals (one small block)
// ---------------------------------------------------------------------------
__global__ void k_scan2() {
    __shared__ int s[128];
    int t = threadIdx.x;
    int v = (t < N_SCANB) ? g_blocksum[t] : 0;
    s[t] = v;
    __syncthreads();
    #pragma unroll
    for (int off = 1; off < 128; off <<= 1) {
        int a = (t >= off) ? s[t - off] : 0;
        __syncthreads();
        s[t] += a;
        __syncthreads();
    }
    if (t < N_SCANB) g_blockoff[t] = s[t] - v;     // exclusive
}

// ---------------------------------------------------------------------------
// 3c) add block offsets; init cursors; finalize rowptr[N]
// ---------------------------------------------------------------------------
__global__ void k_scan3() {
    int i = blockIdx.x * blockDim.x + threadIdx.x;
    if (i < N_NODES) {
        int r = g_rowptr[i] + g_blockoff[i >> 10];
        g_rowptr[i] = r;
        g_cursor[i] = r;
    }
    if (i == 0) g_rowptr[N_NODES] = N_EDGES;
}

// ---------------------------------------------------------------------------
// 4) bucket-scatter edges into CSR slots (packed col+val)
// ---------------------------------------------------------------------------
__global__ void k_scatter(const int* __restrict__ erow,
                          const int* __restrict__ ecol,
                          const float* __restrict__ eval) {
    int e = blockIdx.x * blockDim.x + threadIdx.x;
    if (e >= N_EDGES) return;
    int row = erow[e];
    int pos = atomicAdd(&g_cursor[row], 1);
    g_colval[pos] = make_uint2((unsigned)ecol[e], __float_as_uint(eval[e]));
}

// ---------------------------------------------------------------------------
// 5) pull phase: 16 threads per node, one float4 chunk each.
//    Broadcast (col,val) loads, register accumulation, coalesced store.
// ---------------------------------------------------------------------------
__global__ void k_pull(const float4* __restrict__ x4, float4* __restrict__ out4) {
    int gid = blockIdx.x * blockDim.x + threadIdx.x;
    int n = gid >> 4;            // node
    int c = gid & 15;            // float4 chunk
    if (n >= N_NODES) return;

    int j   = g_rowptr[n];
    int end = g_rowptr[n + 1];

    float4 acc = make_float4(0.f, 0.f, 0.f, 0.f);

    // unrolled by 2 for memory-level parallelism
    for (; j + 2 <= end; j += 2) {
        uint2 cv0 = __ldg(&g_colval[j]);
        uint2 cv1 = __ldg(&g_colval[j + 1]);
        float4 xv0 = __ldg(&x4[(long long)cv0.x * CHUNKS + c]);
        float4 xv1 = __ldg(&x4[(long long)cv1.x * CHUNKS + c]);
        float v0 = __uint_as_float(cv0.y);
        float v1 = __uint_as_float(cv1.y);
        acc.x += v0 * xv0.x + v1 * xv1.x;
        acc.y += v0 * xv0.y + v1 * xv1.y;
        acc.z += v0 * xv0.z + v1 * xv1.z;
        acc.w += v0 * xv0.w + v1 * xv1.w;
    }
    if (j < end) {
        uint2 cv = __ldg(&g_colval[j]);
        float4 xv = __ldg(&x4[(long long)cv.x * CHUNKS + c]);
        float v = __uint_as_float(cv.y);
        acc.x += v * xv.x;
        acc.y += v * xv.y;
        acc.z += v * xv.z;
        acc.w += v * xv.w;
    }

    out4[(long long)n * CHUNKS + c] = acc;
}

// ---------------------------------------------------------------------------
extern "C" void kernel_launch(void* const* d_in, const int* in_sizes, int n_in,
                              void* d_out, int out_size) {
    // Input order: t, x, edge_row, edge_col, edge_val
    const float* x    = (const float*)d_in[1];
    const int*   erow = (const int*)d_in[2];
    const int*   ecol = (const int*)d_in[3];
    const float* ev   = (const float*)d_in[4];
    float*       out  = (float*)d_out;

    const int T = 256;

    k_zero_counts<<<(N_NODES + T - 1) / T, T>>>();
    k_hist<<<(N_EDGES + T - 1) / T, T>>>(erow);
    k_scan1<<<N_SCANB, SCAN_BLK>>>();
    k_scan2<<<1, 128>>>();
    k_scan3<<<(N_NODES + T - 1) / T, T>>>();
    k_scatter<<<(N_EDGES + T - 1) / T, T>>>(erow, ecol, ev);

    long long pull_threads = (long long)N_NODES * CHUNKS;   // 1.6M
    k_pull<<<(int)((pull_threads + T - 1) / T), T>>>((const float4*)x, (float4*)out);
}